// round 6
// baseline (speedup 1.0000x reference)
#include <cuda_runtime.h>
#include <cuda_bf16.h>
#include <math.h>
#include <stdint.h>

#define DMODEL 1024
#define TLEN   1024
#define BATCH  2
#define NHEAD  16
#define HS     64
#define NEXP   8
#define FFDIM  4096
#define NTOK   (BATCH*TLEN)          // 2048
#define QKVN   (3*DMODEL)            // 3072
#define GROWS  (2*NTOK + 192)        // gathered rows capacity (+pad for tile overread)

// ---------------- scratch (__device__ globals; no allocs) ----------------
// pre-split packed bf16x2 weights, K-major [N][K/2] u32 (lo16 = even k)
__device__ uint32_t g_wqkvh[(size_t)QKVN*DMODEL/2];
__device__ uint32_t g_wqkvl[(size_t)QKVN*DMODEL/2];
__device__ uint32_t g_w1h[(size_t)NEXP*FFDIM*DMODEL/2];
__device__ uint32_t g_w1l[(size_t)NEXP*FFDIM*DMODEL/2];
__device__ uint32_t g_w2h[(size_t)NEXP*DMODEL*FFDIM/2];
__device__ uint32_t g_w2l[(size_t)NEXP*DMODEL*FFDIM/2];
// packed activations
__device__ uint32_t g_xh[(size_t)NTOK*DMODEL/2];        // x packed (QKV A)
__device__ uint32_t g_xl[(size_t)NTOK*DMODEL/2];
__device__ uint32_t g_xgh[(size_t)GROWS*DMODEL/2];      // gathered y packed (up A)
__device__ uint32_t g_xgl[(size_t)GROWS*DMODEL/2];
__device__ uint32_t g_hbh[(size_t)GROWS*FFDIM/2];       // relu(up) packed (down A)
__device__ uint32_t g_hbl[(size_t)GROWS*FFDIM/2];

__device__ float g_qkvtmp[(size_t)NTOK*QKVN];           // [2048,3072]
__device__ float g_attn[(size_t)NTOK*DMODEL];           // [b,t,d] concat
__device__ float g_y[(size_t)NTOK*DMODEL];
__device__ float g_topw[NTOK*2];
__device__ int   g_topi[NTOK*2];
__device__ int   g_rowpos[NTOK*2];
__device__ int   g_count[NEXP];
__device__ int   g_offset[NEXP];
__device__ int   g_cursor[NEXP];
__device__ float g_eo[(size_t)GROWS*DMODEL];

// ================= bf16x3 split-precision mma helpers =================
__device__ __forceinline__ void mma_bf16(float d[4], const uint32_t a[4], const uint32_t b[2]) {
    asm volatile(
        "mma.sync.aligned.m16n8k16.row.col.f32.bf16.bf16.f32 "
        "{%0,%1,%2,%3}, {%4,%5,%6,%7}, {%8,%9}, {%0,%1,%2,%3};"
        : "+f"(d[0]), "+f"(d[1]), "+f"(d[2]), "+f"(d[3])
        : "r"(a[0]), "r"(a[1]), "r"(a[2]), "r"(a[3]), "r"(b[0]), "r"(b[1]));
}
// split (x,y) into packed bf16x2 hi and lo words; x -> low 16 bits (even k)
__device__ __forceinline__ void split2(float x, float y, uint32_t& h, uint32_t& l) {
    unsigned short hx = __bfloat16_as_ushort(__float2bfloat16_rn(x));
    unsigned short hy = __bfloat16_as_ushort(__float2bfloat16_rn(y));
    float fx = __uint_as_float(((uint32_t)hx) << 16);
    float fy = __uint_as_float(((uint32_t)hy) << 16);
    unsigned short lx = __bfloat16_as_ushort(__float2bfloat16_rn(x - fx));
    unsigned short ly = __bfloat16_as_ushort(__float2bfloat16_rn(y - fy));
    h = ((uint32_t)hy << 16) | (uint32_t)hx;
    l = ((uint32_t)ly << 16) | (uint32_t)lx;
}

// ================= bf16x3 GEMM body: 128x128 tile, Kchunk=16, 256 thr =================
// A, B: pre-split packed u32 [rows][ld words]. Optional packed C output (CH/CL).
#define LDW 12   // u32 words per row (8 used + 4 pad)

__device__ __forceinline__ void gemm_mma_body(
    const uint32_t* __restrict__ AH, const uint32_t* __restrict__ AL, int ldaw,
    const uint32_t* __restrict__ BH, const uint32_t* __restrict__ BL, int ldbw,
    float* __restrict__ C, int ldc,
    int K, int Mvalid, const float* __restrict__ bias, bool relu,
    uint32_t* __restrict__ CH, uint32_t* __restrict__ CL, int ldcw)
{
    __shared__ uint32_t AsH[128*LDW];
    __shared__ uint32_t AsL[128*LDW];
    __shared__ uint32_t BsH[128*LDW];
    __shared__ uint32_t BsL[128*LDW];

    const int tid = threadIdx.x;
    const int wid = tid >> 5, lane = tid & 31;
    const int grp = lane >> 2, tig = lane & 3;
    const int m_base = (wid >> 2) * 64;   // 2 warp-rows of 64
    const int n_base = (wid & 3) * 32;    // 4 warp-cols of 32

    float acc[4][4][4];
#pragma unroll
    for (int mt = 0; mt < 4; mt++)
#pragma unroll
        for (int nt = 0; nt < 4; nt++)
#pragma unroll
            for (int i = 0; i < 4; i++) acc[mt][nt][i] = 0.f;

    // loaders: 2 threads per row, uint4 each (8 k values)
    const int br = tid >> 1;
    const int hh = tid & 1;
    const size_t Apw = (size_t)br * ldaw + hh * 4;
    const size_t Bpw = (size_t)br * ldbw + hh * 4;
    const int sidx = br * LDW + hh * 4;

    uint4 rah = *(const uint4*)(AH + Apw);
    uint4 ral = *(const uint4*)(AL + Apw);
    uint4 rbh = *(const uint4*)(BH + Bpw);
    uint4 rbl = *(const uint4*)(BL + Bpw);

    const int T = K >> 4;
    for (int kb = 0; kb < T; kb++) {
        __syncthreads();
        *(uint4*)&AsH[sidx] = rah;
        *(uint4*)&AsL[sidx] = ral;
        *(uint4*)&BsH[sidx] = rbh;
        *(uint4*)&BsL[sidx] = rbl;
        __syncthreads();
        if (kb + 1 < T) {
            size_t off = (size_t)(kb + 1) * 8;
            rah = *(const uint4*)(AH + Apw + off);
            ral = *(const uint4*)(AL + Apw + off);
            rbh = *(const uint4*)(BH + Bpw + off);
            rbl = *(const uint4*)(BL + Bpw + off);
        }

        uint32_t bH[4][2], bL[4][2];
#pragma unroll
        for (int nt = 0; nt < 4; nt++) {
            int col = n_base + nt*8 + grp;
            bH[nt][0] = BsH[col*LDW + tig];
            bH[nt][1] = BsH[col*LDW + tig + 4];
            bL[nt][0] = BsL[col*LDW + tig];
            bL[nt][1] = BsL[col*LDW + tig + 4];
        }
#pragma unroll
        for (int mt = 0; mt < 4; mt++) {
            int row  = m_base + mt*16 + grp;
            int row8 = row + 8;
            uint32_t aH[4], aL[4];
            aH[0] = AsH[row *LDW + tig];     aH[1] = AsH[row8*LDW + tig];
            aH[2] = AsH[row *LDW + tig + 4]; aH[3] = AsH[row8*LDW + tig + 4];
            aL[0] = AsL[row *LDW + tig];     aL[1] = AsL[row8*LDW + tig];
            aL[2] = AsL[row *LDW + tig + 4]; aL[3] = AsL[row8*LDW + tig + 4];
#pragma unroll
            for (int nt = 0; nt < 4; nt++) {
                mma_bf16(acc[mt][nt], aH, bH[nt]);
                mma_bf16(acc[mt][nt], aH, bL[nt]);
                mma_bf16(acc[mt][nt], aL, bH[nt]);
            }
        }
    }

    // epilogue: lane (grp,tig) owns rows (row,row+8), cols (col,col+1), col even
#pragma unroll
    for (int mt = 0; mt < 4; mt++) {
        int row = m_base + mt*16 + grp;
#pragma unroll
        for (int nt = 0; nt < 4; nt++) {
            int col = n_base + nt*8 + tig*2;
            float v0 = acc[mt][nt][0], v1 = acc[mt][nt][1];
            float v2 = acc[mt][nt][2], v3 = acc[mt][nt][3];
            if (bias) {
                float b0 = bias[col], b1 = bias[col+1];
                v0 += b0; v1 += b1; v2 += b0; v3 += b1;
            }
            if (relu) {
                v0 = fmaxf(v0, 0.f); v1 = fmaxf(v1, 0.f);
                v2 = fmaxf(v2, 0.f); v3 = fmaxf(v3, 0.f);
            }
            if (CH) {
                // packed bf16-pair output (cols (col,col+1) form one k-pair)
                uint32_t h, l;
                if (row < Mvalid) {
                    split2(v0, v1, h, l);
                    size_t o = (size_t)row * ldcw + (col >> 1);
                    CH[o] = h; CL[o] = l;
                }
                if (row + 8 < Mvalid) {
                    split2(v2, v3, h, l);
                    size_t o = (size_t)(row+8) * ldcw + (col >> 1);
                    CH[o] = h; CL[o] = l;
                }
            } else {
                if (row < Mvalid) {
                    float2 p; p.x = v0; p.y = v1;
                    *(float2*)(C + (size_t)row * ldc + col) = p;
                }
                if (row + 8 < Mvalid) {
                    float2 p; p.x = v2; p.y = v3;
                    *(float2*)(C + (size_t)(row+8) * ldc + col) = p;
                }
            }
        }
    }
}

// ---------------- GEMM wrappers ----------------
__global__ void __launch_bounds__(256, 2) k_gemm_qkv()
{
    int n0 = blockIdx.x * 128, m0 = blockIdx.y * 128;
    gemm_mma_body(g_xh + (size_t)m0 * (DMODEL/2), g_xl + (size_t)m0 * (DMODEL/2), DMODEL/2,
                  g_wqkvh + (size_t)n0 * (DMODEL/2), g_wqkvl + (size_t)n0 * (DMODEL/2), DMODEL/2,
                  g_qkvtmp + (size_t)m0 * QKVN + n0, QKVN,
                  DMODEL, 128, nullptr, false, nullptr, nullptr, 0);
}
__global__ void __launch_bounds__(256, 2) k_gemm_up(const float* __restrict__ b1)
{
    int e = blockIdx.z;
    int cnt = g_count[e];
    int m0 = blockIdx.y * 128;
    if (m0 >= cnt) return;
    int base = g_offset[e] + m0;
    int n0 = blockIdx.x * 128;
    int vr = cnt - m0; if (vr > 128) vr = 128;
    const size_t wb = (size_t)e * FFDIM * (DMODEL/2) + (size_t)n0 * (DMODEL/2);
    gemm_mma_body(g_xgh + (size_t)base * (DMODEL/2), g_xgl + (size_t)base * (DMODEL/2), DMODEL/2,
                  g_w1h + wb, g_w1l + wb, DMODEL/2,
                  nullptr, 0,
                  DMODEL, vr, b1 + (size_t)e * FFDIM + n0, true,
                  g_hbh + (size_t)base * (FFDIM/2) + (n0 >> 1),
                  g_hbl + (size_t)base * (FFDIM/2) + (n0 >> 1), FFDIM/2);
}
__global__ void __launch_bounds__(256, 2) k_gemm_down(const float* __restrict__ b2)
{
    int e = blockIdx.z;
    int cnt = g_count[e];
    int m0 = blockIdx.y * 128;
    if (m0 >= cnt) return;
    int base = g_offset[e] + m0;
    int n0 = blockIdx.x * 128;
    int vr = cnt - m0; if (vr > 128) vr = 128;
    const size_t wb = (size_t)e * DMODEL * (FFDIM/2) + (size_t)n0 * (FFDIM/2);
    gemm_mma_body(g_hbh + (size_t)base * (FFDIM/2), g_hbl + (size_t)base * (FFDIM/2), FFDIM/2,
                  g_w2h + wb, g_w2l + wb, FFDIM/2,
                  g_eo + (size_t)base * DMODEL + n0, DMODEL,
                  FFDIM, vr, b2 + (size_t)e * DMODEL + n0, false,
                  nullptr, nullptr, 0);
}

// ---------------- transpose + bf16 split: in[z][R][C] fp32 -> out[z][C][R/2] packed u32 ----------------
__global__ void k_tsplit(const float* __restrict__ in,
                         uint32_t* __restrict__ outH, uint32_t* __restrict__ outL,
                         int R, int C)
{
    __shared__ float t[32][33];
    in   += (size_t)blockIdx.z * R * C;
    outH += (size_t)blockIdx.z * C * (R/2);
    outL += (size_t)blockIdx.z * C * (R/2);
    int c0 = blockIdx.x * 32, r0 = blockIdx.y * 32;
    int tid = threadIdx.x;
    int lr = tid >> 5, tx = tid & 31;
#pragma unroll
    for (int i = 0; i < 4; i++)
        t[lr + 8*i][tx] = in[(size_t)(r0 + lr + 8*i) * C + c0 + tx];
    __syncthreads();
#pragma unroll
    for (int rep = 0; rep < 2; rep++) {
        int w = tid + rep*256;
        int c = w >> 4, rp = w & 15;
        uint32_t h, l;
        split2(t[2*rp][c], t[2*rp+1][c], h, l);
        size_t o = (size_t)(c0 + c) * (R/2) + (r0 >> 1) + rp;
        outH[o] = h; outL[o] = l;
    }
}

// ---------------- split x rows (row-major, no transpose) ----------------
__global__ void k_splitx(const float* __restrict__ in,
                         uint32_t* __restrict__ outH, uint32_t* __restrict__ outL)
{
    int n = blockIdx.x, tid = threadIdx.x;
    float4 v = *(const float4*)(in + (size_t)n*DMODEL + tid*4);
    uint32_t h0, l0, h1, l1;
    split2(v.x, v.y, h0, l0);
    split2(v.z, v.w, h1, l1);
    uint2 ph; ph.x = h0; ph.y = h1;
    uint2 pl; pl.x = l0; pl.y = l1;
    *(uint2*)(outH + (size_t)n*(DMODEL/2) + tid*2) = ph;
    *(uint2*)(outL + (size_t)n*(DMODEL/2) + tid*2) = pl;
}

// ---------------- K2: causal flash attention, Br=64, Bc=32, 128 thr, 4x4 reg tiles ----------------
__global__ void k_attn()
{
    int qt = blockIdx.x;
    int bh = blockIdx.y;
    int b = bh >> 4, h = bh & 15;
    const float* Qp = g_qkvtmp + ((size_t)b * TLEN + qt * 64) * QKVN + h * 64;
    const float* Kp = g_qkvtmp + (size_t)b * TLEN * QKVN + DMODEL + h * 64;
    const float* Vp = g_qkvtmp + (size_t)b * TLEN * QKVN + 2 * DMODEL + h * 64;

    __shared__ float Qs[64][65];
    __shared__ float Ks[32][65];
    __shared__ float Vs[32][68];
    __shared__ float Ps[64][36];

    const int tid = threadIdx.x;          // 128
    const int ty = tid >> 3, tx = tid & 7;
    const int r0 = ty * 4;
    const int c0 = tx * 4;
    const int d0 = tx * 8;
    const float scale = 0.03125f;

    {
        int lr = tid >> 1, lc = (tid & 1) * 32;
#pragma unroll
        for (int i = 0; i < 8; i++) {
            float4 v = *(const float4*)(Qp + (size_t)lr * QKVN + lc + i*4);
            Qs[lr][lc+i*4+0] = v.x; Qs[lr][lc+i*4+1] = v.y;
            Qs[lr][lc+i*4+2] = v.z; Qs[lr][lc+i*4+3] = v.w;
        }
    }

    float m_i[4], l_i[4], o[4][8];
#pragma unroll
    for (int i = 0; i < 4; i++) {
        m_i[i] = -1e30f; l_i[i] = 0.f;
#pragma unroll
        for (int d = 0; d < 8; d++) o[i][d] = 0.f;
    }

    const int nkt = 2*qt + 2;
    for (int kt = 0; kt < nkt; kt++) {
        __syncthreads();
        {
            int lr = tid >> 2, lc = (tid & 3) * 16;
#pragma unroll
            for (int i = 0; i < 4; i++) {
                float4 kv = *(const float4*)(Kp + ((size_t)kt*32 + lr) * QKVN + lc + i*4);
                Ks[lr][lc+i*4+0] = kv.x; Ks[lr][lc+i*4+1] = kv.y;
                Ks[lr][lc+i*4+2] = kv.z; Ks[lr][lc+i*4+3] = kv.w;
                *(float4*)&Vs[lr][lc + i*4] =
                    *(const float4*)(Vp + ((size_t)kt*32 + lr) * QKVN + lc + i*4);
            }
        }
        __syncthreads();

        float s[4][4];
#pragma unroll
        for (int i = 0; i < 4; i++)
#pragma unroll
            for (int j = 0; j < 4; j++) s[i][j] = 0.f;
        for (int kk = 0; kk < 64; kk++) {
            float qv[4], kv[4];
#pragma unroll
            for (int i = 0; i < 4; i++) qv[i] = Qs[r0+i][kk];
#pragma unroll
            for (int j = 0; j < 4; j++) kv[j] = Ks[c0+j][kk];
#pragma unroll
            for (int i = 0; i < 4; i++)
#pragma unroll
                for (int j = 0; j < 4; j++) s[i][j] += qv[i] * kv[j];
        }

        float corr[4];
#pragma unroll
        for (int i = 0; i < 4; i++) {
            int rg = qt*64 + r0 + i;
            float mloc = -1e30f;
#pragma unroll
            for (int j = 0; j < 4; j++) {
                int cg = kt*32 + c0 + j;
                s[i][j] = (cg <= rg) ? s[i][j] * scale : -1e30f;
                mloc = fmaxf(mloc, s[i][j]);
            }
            mloc = fmaxf(mloc, __shfl_xor_sync(0xffffffffu, mloc, 1));
            mloc = fmaxf(mloc, __shfl_xor_sync(0xffffffffu, mloc, 2));
            mloc = fmaxf(mloc, __shfl_xor_sync(0xffffffffu, mloc, 4));
            float mnew = fmaxf(m_i[i], mloc);
            corr[i] = __expf(m_i[i] - mnew);
            float ls = 0.f;
#pragma unroll
            for (int j = 0; j < 4; j++) {
                float p = __expf(s[i][j] - mnew);
                Ps[r0+i][c0+j] = p;
                ls += p;
            }
            ls += __shfl_xor_sync(0xffffffffu, ls, 1);
            ls += __shfl_xor_sync(0xffffffffu, ls, 2);
            ls += __shfl_xor_sync(0xffffffffu, ls, 4);
            l_i[i] = l_i[i] * corr[i] + ls;
            m_i[i] = mnew;
#pragma unroll
            for (int d = 0; d < 8; d++) o[i][d] *= corr[i];
        }
        __syncthreads();

        for (int cc = 0; cc < 32; cc++) {
            float pv[4];
#pragma unroll
            for (int i = 0; i < 4; i++) pv[i] = Ps[r0+i][cc];
            float4 va = *(const float4*)&Vs[cc][d0];
            float4 vb = *(const float4*)&Vs[cc][d0+4];
#pragma unroll
            for (int i = 0; i < 4; i++) {
                o[i][0] += pv[i]*va.x; o[i][1] += pv[i]*va.y;
                o[i][2] += pv[i]*va.z; o[i][3] += pv[i]*va.w;
                o[i][4] += pv[i]*vb.x; o[i][5] += pv[i]*vb.y;
                o[i][6] += pv[i]*vb.z; o[i][7] += pv[i]*vb.w;
            }
        }
    }

#pragma unroll
    for (int i = 0; i < 4; i++) {
        float inv = 1.f / l_i[i];
        float* outp = g_attn + ((size_t)b*TLEN + qt*64 + r0 + i)*DMODEL + h*64 + d0;
        float4 w0, w1;
        w0.x = o[i][0]*inv; w0.y = o[i][1]*inv; w0.z = o[i][2]*inv; w0.w = o[i][3]*inv;
        w1.x = o[i][4]*inv; w1.y = o[i][5]*inv; w1.z = o[i][6]*inv; w1.w = o[i][7]*inv;
        *(float4*)(outp)     = w0;
        *(float4*)(outp + 4) = w1;
    }
}

// ---------------- block reduce ----------------
__device__ __forceinline__ float block_sum(float v)
{
    __shared__ float red[256];
    int tid = threadIdx.x;
    red[tid] = v;
    __syncthreads();
    for (int s = 128; s > 0; s >>= 1) {
        if (tid < s) red[tid] += red[tid + s];
        __syncthreads();
    }
    float r = red[0];
    __syncthreads();
    return r;
}

// ---------------- K3: y = x + LN(attn) ----------------
__global__ void k_ln1(const float* __restrict__ x,
                      const float* __restrict__ g, const float* __restrict__ bln)
{
    int n = blockIdx.x;
    int tid = threadIdx.x;
    float v[4];
#pragma unroll
    for (int i = 0; i < 4; i++) v[i] = g_attn[(size_t)n*DMODEL + tid + i*256];
    float s = v[0] + v[1] + v[2] + v[3];
    s = block_sum(s);
    float mean = s * (1.f/DMODEL);
    float q = 0.f;
#pragma unroll
    for (int i = 0; i < 4; i++) { float dd = v[i] - mean; q += dd*dd; }
    q = block_sum(q);
    float rstd = rsqrtf(q * (1.f/DMODEL) + 1e-5f);
#pragma unroll
    for (int i = 0; i < 4; i++) {
        int d = tid + i*256;
        float ln = (v[i] - mean) * rstd * g[d] + bln[d];
        g_y[(size_t)n*DMODEL + d] = x[(size_t)n*DMODEL + d] + ln;
    }
}

// ---------------- K0: zero routing state ----------------
__global__ void k_zero()
{
    int i = threadIdx.x;
    if (i < NEXP) { g_count[i] = 0; g_cursor[i] = 0; }
}

// ---------------- K4: gate ----------------
__global__ void k_gate(const float* __restrict__ gate_W)
{
    int n = blockIdx.x*8 + (threadIdx.x >> 5);
    int lane = threadIdx.x & 31;
    const float* yr = g_y + (size_t)n*DMODEL;
    float acc[NEXP];
#pragma unroll
    for (int e = 0; e < NEXP; e++) acc[e] = 0.f;
    for (int d = lane; d < DMODEL; d += 32) {
        float yv = yr[d];
        const float* gw = gate_W + (size_t)d*NEXP;
#pragma unroll
        for (int e = 0; e < NEXP; e++) acc[e] += yv * gw[e];
    }
#pragma unroll
    for (int e = 0; e < NEXP; e++)
        for (int off = 16; off; off >>= 1)
            acc[e] += __shfl_xor_sync(0xffffffffu, acc[e], off);
    if (lane == 0) {
        float best = -1e30f; int bi = 0;
#pragma unroll
        for (int e = 0; e < NEXP; e++) if (acc[e] > best) { best = acc[e]; bi = e; }
        float best2 = -1e30f; int bi2 = 0;
#pragma unroll
        for (int e = 0; e < NEXP; e++) if (e != bi && acc[e] > best2) { best2 = acc[e]; bi2 = e; }
        float w0 = 1.f / (1.f + expf(best2 - best));
        g_topw[2*n]   = w0;  g_topw[2*n+1] = 1.f - w0;
        g_topi[2*n]   = bi;  g_topi[2*n+1] = bi2;
        atomicAdd(&g_count[bi],  1);
        atomicAdd(&g_count[bi2], 1);
    }
}

// ---------------- K5: offsets ----------------
__global__ void k_offs()
{
    if (threadIdx.x == 0) {
        int o = 0;
        for (int e = 0; e < NEXP; e++) { g_offset[e] = o; o += g_count[e]; }
    }
}

// ---------------- K6: gather + split (packed output) ----------------
__global__ void k_gather()
{
    int p = blockIdx.x;
    int n = p >> 1;
    __shared__ int spos;
    if (threadIdx.x == 0) {
        int e = g_topi[p];
        int pos = g_offset[e] + atomicAdd(&g_cursor[e], 1);
        g_rowpos[p] = pos;
        spos = pos;
    }
    __syncthreads();
    int pos = spos;
    int tid = threadIdx.x;
    float4 v = *(const float4*)(g_y + (size_t)n*DMODEL + tid*4);
    uint32_t h0, l0, h1, l1;
    split2(v.x, v.y, h0, l0);
    split2(v.z, v.w, h1, l1);
    uint2 ph; ph.x = h0; ph.y = h1;
    uint2 pl; pl.x = l0; pl.y = l1;
    *(uint2*)(g_xgh + (size_t)pos*(DMODEL/2) + tid*2) = ph;
    *(uint2*)(g_xgl + (size_t)pos*(DMODEL/2) + tid*2) = pl;
}

// ---------------- K9: combine + LN2 + residual ----------------
__global__ void k_out(const float* __restrict__ g, const float* __restrict__ bln,
                      float* __restrict__ out)
{
    int n = blockIdx.x;
    int tid = threadIdx.x;
    int r0 = g_rowpos[2*n], r1 = g_rowpos[2*n+1];
    float w0 = g_topw[2*n], w1 = g_topw[2*n+1];
    float v[4];
#pragma unroll
    for (int i = 0; i < 4; i++) {
        int d = tid + i*256;
        v[i] = w0 * g_eo[(size_t)r0*DMODEL + d] + w1 * g_eo[(size_t)r1*DMODEL + d];
    }
    float s = v[0] + v[1] + v[2] + v[3];
    s = block_sum(s);
    float mean = s * (1.f/DMODEL);
    float q = 0.f;
#pragma unroll
    for (int i = 0; i < 4; i++) { float dd = v[i] - mean; q += dd*dd; }
    q = block_sum(q);
    float rstd = rsqrtf(q * (1.f/DMODEL) + 1e-5f);
#pragma unroll
    for (int i = 0; i < 4; i++) {
        int d = tid + i*256;
        float ln = (v[i] - mean) * rstd * g[d] + bln[d];
        out[(size_t)n*DMODEL + d] = g_y[(size_t)n*DMODEL + d] + ln;
    }
}

// ---------------- launch ----------------
extern "C" void kernel_launch(void* const* d_in, const int* in_sizes, int n_in,
                              void* d_out, int out_size)
{
    const float* x      = (const float*)d_in[0];
    const float* Wq     = (const float*)d_in[1];
    const float* Wk     = (const float*)d_in[2];
    const float* Wv     = (const float*)d_in[3];
    const float* gate_W = (const float*)d_in[4];
    const float* W1     = (const float*)d_in[5];
    const float* b1     = (const float*)d_in[6];
    const float* W2     = (const float*)d_in[7];
    const float* b2     = (const float*)d_in[8];
    const float* ln1g   = (const float*)d_in[9];
    const float* ln1b   = (const float*)d_in[10];
    const float* ln2g   = (const float*)d_in[11];
    const float* ln2b   = (const float*)d_in[12];
    float* out = (float*)d_out;

    uint32_t *p_wqkvh, *p_wqkvl, *p_w1h, *p_w1l, *p_w2h, *p_w2l, *p_xh, *p_xl;
    cudaGetSymbolAddress((void**)&p_wqkvh, g_wqkvh);
    cudaGetSymbolAddress((void**)&p_wqkvl, g_wqkvl);
    cudaGetSymbolAddress((void**)&p_w1h,   g_w1h);
    cudaGetSymbolAddress((void**)&p_w1l,   g_w1l);
    cudaGetSymbolAddress((void**)&p_w2h,   g_w2h);
    cudaGetSymbolAddress((void**)&p_w2l,   g_w2l);
    cudaGetSymbolAddress((void**)&p_xh,    g_xh);
    cudaGetSymbolAddress((void**)&p_xl,    g_xl);

    k_zero<<<1, 32>>>();
    k_splitx<<<NTOK, 256>>>(x, p_xh, p_xl);
    // weight transpose + bf16 hi/lo split, K-major packed output
    k_tsplit<<<dim3(2, 32, 16), 256>>>(Wq, p_wqkvh,            p_wqkvl,            DMODEL, HS);
    k_tsplit<<<dim3(2, 32, 16), 256>>>(Wk, p_wqkvh + 1024*512, p_wqkvl + 1024*512, DMODEL, HS);
    k_tsplit<<<dim3(2, 32, 16), 256>>>(Wv, p_wqkvh + 2048*512, p_wqkvl + 2048*512, DMODEL, HS);
    k_tsplit<<<dim3(FFDIM/32, DMODEL/32, NEXP), 256>>>(W1, p_w1h, p_w1l, DMODEL, FFDIM);
    k_tsplit<<<dim3(DMODEL/32, FFDIM/32, NEXP), 256>>>(W2, p_w2h, p_w2l, FFDIM, DMODEL);

    k_gemm_qkv<<<dim3(QKVN/128, NTOK/128), 256>>>();
    k_attn    <<<dim3(TLEN/64, BATCH*NHEAD), 128>>>();
    k_ln1     <<<NTOK, 256>>>(x, ln1g, ln1b);
    k_gate    <<<NTOK/8, 256>>>(gate_W);
    k_offs    <<<1, 1>>>();
    k_gather  <<<NTOK*2, 256>>>();
    k_gemm_up  <<<dim3(FFDIM/128, NTOK/128, NEXP), 256>>>(b1);
    k_gemm_down<<<dim3(DMODEL/128, NTOK/128, NEXP), 256>>>(b2);
    k_out     <<<NTOK, 256>>>(ln2g, ln2b, out);
}